// round 1
// baseline (speedup 1.0000x reference)
#include <cuda_runtime.h>
#include <math.h>
#include <stdint.h>
#include <stddef.h>

#define BATCH_N 65536
#define QDIM    256
#define BM 128
#define BN 128
#define BK 16

// ---------------- scratch (allocation-free: __device__ globals) ----------------
static __device__ float g_h[(size_t)BATCH_N * 768];          // wide hidden (768/512) + nl temp
static __device__ float g_bufs[3][(size_t)BATCH_N * QDIM];   // rotating 256-wide activation buffers
static __device__ float g_tent[8 * QDIM * QDIM];             // tanh(ent[li])
static __device__ float g_gate[4][8 * QDIM];                 // lin, p3, p4, p5

struct EpiParams {
    const float* bias;
    const float* cmat;    // elementwise companion matrix (cur / cur2), ld = ldc
    const float* resmat;  // residual matrix, ld = ldc
    const float* lin;     // per-column gate params (256)
    const float* p3;
    const float* p4;
    const float* p5;
    float alpha;
    int   blend;
};

enum { E_BIAS = 0, E_SILU = 1, E_TANH = 2, E_GATE = 3, E_NL = 4 };

// ---------------- templated SGEMM: C[M,N] = A[M,K] @ B[K,N] (+ epilogue) -------
template <int EPI>
__global__ void __launch_bounds__(256, 2) sgemm_k(
    const float* __restrict__ A, int lda,
    const float* __restrict__ B, int ldb,
    float* __restrict__ C, int ldc,
    int K, EpiParams ep)
{
    __shared__ __align__(16) float As[BK][BM + 4];  // [k][m], padded vs STS conflicts
    __shared__ __align__(16) float Bs[BK][BN];      // [k][n]

    const int tid = threadIdx.x;
    const int tx  = tid & 15;
    const int ty  = tid >> 4;
    const int m0  = blockIdx.y * BM;
    const int n0  = blockIdx.x * BN;

    // global->smem load mapping: 2 float4 per thread for A tile (128x16) and B tile (16x128)
    const int g0 = tid, g1 = tid + 256;
    const int ar0 = g0 >> 2, ac0 = (g0 & 3) * 4;
    const int ar1 = g1 >> 2, ac1 = (g1 & 3) * 4;
    const int br0 = g0 >> 5, bc0 = (g0 & 31) * 4;
    const int br1 = g1 >> 5, bc1 = (g1 & 31) * 4;

    const float* pa0 = A + (size_t)(m0 + ar0) * lda + ac0;
    const float* pa1 = A + (size_t)(m0 + ar1) * lda + ac1;
    const float* pb0 = B + (size_t)br0 * ldb + n0 + bc0;
    const float* pb1 = B + (size_t)br1 * ldb + n0 + bc1;

    float acc[8][8];
#pragma unroll
    for (int i = 0; i < 8; i++)
#pragma unroll
        for (int j = 0; j < 8; j++) acc[i][j] = 0.0f;

    float4 ra0 = *(const float4*)pa0;
    float4 ra1 = *(const float4*)pa1;
    float4 rb0 = *(const float4*)pb0;
    float4 rb1 = *(const float4*)pb1;

    const int ktiles = K / BK;
    for (int kt = 0; kt < ktiles; kt++) {
        As[ac0 + 0][ar0] = ra0.x; As[ac0 + 1][ar0] = ra0.y;
        As[ac0 + 2][ar0] = ra0.z; As[ac0 + 3][ar0] = ra0.w;
        As[ac1 + 0][ar1] = ra1.x; As[ac1 + 1][ar1] = ra1.y;
        As[ac1 + 2][ar1] = ra1.z; As[ac1 + 3][ar1] = ra1.w;
        *(float4*)&Bs[br0][bc0] = rb0;
        *(float4*)&Bs[br1][bc1] = rb1;
        __syncthreads();

        pa0 += BK; pa1 += BK;
        pb0 += (size_t)BK * ldb; pb1 += (size_t)BK * ldb;
        if (kt + 1 < ktiles) {  // prefetch next tile while computing this one
            ra0 = *(const float4*)pa0; ra1 = *(const float4*)pa1;
            rb0 = *(const float4*)pb0; rb1 = *(const float4*)pb1;
        }

#pragma unroll
        for (int k = 0; k < BK; k++) {
            float a[8], b[8];
            *(float4*)&a[0] = *(const float4*)&As[k][ty * 8];
            *(float4*)&a[4] = *(const float4*)&As[k][ty * 8 + 4];
            *(float4*)&b[0] = *(const float4*)&Bs[k][tx * 8];
            *(float4*)&b[4] = *(const float4*)&Bs[k][tx * 8 + 4];
#pragma unroll
            for (int i = 0; i < 8; i++)
#pragma unroll
                for (int j = 0; j < 8; j++) acc[i][j] += a[i] * b[j];
        }
        __syncthreads();
    }

    // -------- epilogue --------
    const int nb = n0 + tx * 8;
    float bias8[8], lin8[8], p38[8], p48[8], p58[8];
    if (EPI != E_GATE) {
#pragma unroll
        for (int j = 0; j < 8; j++) bias8[j] = ep.bias[nb + j];
    }
    if (EPI == E_GATE) {
#pragma unroll
        for (int j = 0; j < 8; j++) {
            lin8[j] = ep.lin[nb + j];
            p38[j]  = ep.p3[nb + j];
            p48[j]  = ep.p4[nb + j];
            p58[j]  = ep.p5[nb + j];
        }
    }

#pragma unroll
    for (int i = 0; i < 8; i++) {
        const int m = m0 + ty * 8 + i;
        const size_t rowo = (size_t)m * ldc + nb;
        float out8[8];
#pragma unroll
        for (int j = 0; j < 8; j++) {
            float v = acc[i][j];
            if (EPI == E_BIAS) {
                v += bias8[j];
            } else if (EPI == E_SILU) {
                v += bias8[j];
                v = v / (1.0f + expf(-v));
            } else if (EPI == E_TANH) {
                v += bias8[j];
                v = tanhf(v);
            } else if (EPI == E_GATE) {
                const float c = ep.cmat[rowo + j];
                const float g = (lin8[j] * c
                                 + 0.5f * sinf(p38[j] * c + p48[j])
                                 + 0.5f * cosf(p58[j] * c)) * 0.25f;
                v = (c + 0.3f * g + 0.2f * v) * (1.0f / 1.5f);
                if (ep.blend)
                    v = ep.alpha * v + (1.0f - ep.alpha) * ep.resmat[rowo + j];
            } else if (EPI == E_NL) {
                v += bias8[j];
                const float c2 = ep.cmat[rowo + j];
                v = ep.alpha * (c2 + 0.1f * v) + (1.0f - ep.alpha) * ep.resmat[rowo + j];
            }
            out8[j] = v;
        }
        *(float4*)&C[rowo]     = make_float4(out8[0], out8[1], out8[2], out8[3]);
        *(float4*)&C[rowo + 4] = make_float4(out8[4], out8[5], out8[6], out8[7]);
    }
}

// ---------------- LayerNorm (over 768) + exact gelu, in place -------------------
__global__ void ln_gelu_k(float* __restrict__ h,
                          const float* __restrict__ w,
                          const float* __restrict__ b)
{
    const int row = blockIdx.x;
    float* hr = h + (size_t)row * 768;
    const int t = threadIdx.x;

    const float v0 = hr[t], v1 = hr[t + 256], v2 = hr[t + 512];
    float s  = v0 + v1 + v2;
    float ss = v0 * v0 + v1 * v1 + v2 * v2;

#pragma unroll
    for (int o = 16; o > 0; o >>= 1) {
        s  += __shfl_down_sync(0xffffffffu, s, o);
        ss += __shfl_down_sync(0xffffffffu, ss, o);
    }
    __shared__ float rs[8], rss[8];
    __shared__ float mu_s, rstd_s;
    const int lane = t & 31, wp = t >> 5;
    if (lane == 0) { rs[wp] = s; rss[wp] = ss; }
    __syncthreads();
    if (t == 0) {
        float S = 0.0f, SS = 0.0f;
#pragma unroll
        for (int k = 0; k < 8; k++) { S += rs[k]; SS += rss[k]; }
        const float mu  = S * (1.0f / 768.0f);
        const float var = SS * (1.0f / 768.0f) - mu * mu;
        mu_s = mu;
        rstd_s = rsqrtf(var + 1e-5f);
    }
    __syncthreads();
    const float mu = mu_s, rstd = rstd_s;

#pragma unroll
    for (int k = 0; k < 3; k++) {
        const int c = t + k * 256;
        float x = (((k == 0) ? v0 : (k == 1) ? v1 : v2) - mu) * rstd * w[c] + b[c];
        hr[c] = 0.5f * x * (1.0f + erff(x * 0.70710678118654752f));
    }
}

// ---------------- row L2-normalize (256) + tanh -------------------------------
__global__ void norm_tanh_k(const float* __restrict__ in, float* __restrict__ out)
{
    const int wp = threadIdx.x >> 5, lane = threadIdx.x & 31;
    const size_t row = (size_t)blockIdx.x * 8 + wp;
    const float* r = in + row * QDIM;
    const float4 a = *(const float4*)(r + lane * 4);
    const float4 c = *(const float4*)(r + 128 + lane * 4);
    float s = a.x * a.x + a.y * a.y + a.z * a.z + a.w * a.w
            + c.x * c.x + c.y * c.y + c.z * c.z + c.w * c.w;
#pragma unroll
    for (int o = 16; o > 0; o >>= 1) s += __shfl_xor_sync(0xffffffffu, s, o);
    const float inv = 1.0f / (sqrtf(s) + 1e-8f);
    float* o = out + row * QDIM;
    *(float4*)(o + lane * 4) =
        make_float4(tanhf(a.x * inv), tanhf(a.y * inv), tanhf(a.z * inv), tanhf(a.w * inv));
    *(float4*)(o + 128 + lane * 4) =
        make_float4(tanhf(c.x * inv), tanhf(c.y * inv), tanhf(c.z * inv), tanhf(c.w * inv));
}

// ---------------- prep: tanh(ent), gate param folding -------------------------
__global__ void prep_k(const float* __restrict__ ent, const float* __restrict__ gp,
                       float* __restrict__ tent, float* __restrict__ lin,
                       float* __restrict__ p3, float* __restrict__ p4,
                       float* __restrict__ p5)
{
    const int i = blockIdx.x * blockDim.x + threadIdx.x;
    if (i < 8 * QDIM * QDIM) tent[i] = tanhf(ent[i]);
    if (i < 8 * QDIM) {
        const float* p = gp + (size_t)i * 6;
        lin[i] = sinf(p[0]) + cosf(p[1]) + tanhf(p[2]);
        p3[i] = p[3]; p4[i] = p[4]; p5[i] = p[5];
    }
}

// ---------------- host orchestration ------------------------------------------
static void launch_gemm(int epi, const float* A, int lda, const float* B, int ldb,
                        float* C, int ldc, int K, int N, const EpiParams& ep)
{
    dim3 grid(N / BN, BATCH_N / BM);
    dim3 blk(256);
    switch (epi) {
        case E_BIAS: sgemm_k<E_BIAS><<<grid, blk>>>(A, lda, B, ldb, C, ldc, K, ep); break;
        case E_SILU: sgemm_k<E_SILU><<<grid, blk>>>(A, lda, B, ldb, C, ldc, K, ep); break;
        case E_TANH: sgemm_k<E_TANH><<<grid, blk>>>(A, lda, B, ldb, C, ldc, K, ep); break;
        case E_GATE: sgemm_k<E_GATE><<<grid, blk>>>(A, lda, B, ldb, C, ldc, K, ep); break;
        case E_NL:   sgemm_k<E_NL>  <<<grid, blk>>>(A, lda, B, ldb, C, ldc, K, ep); break;
    }
}

extern "C" void kernel_launch(void* const* d_in, const int* in_sizes, int n_in,
                              void* d_out, int out_size)
{
    (void)in_sizes; (void)n_in; (void)out_size;
    const float* x    = (const float*)d_in[0];
    const float* w01  = (const float*)d_in[1];
    const float* b01  = (const float*)d_in[2];
    const float* lnw  = (const float*)d_in[3];
    const float* lnb  = (const float*)d_in[4];
    const float* w02  = (const float*)d_in[5];
    const float* b02  = (const float*)d_in[6];
    const float* w11  = (const float*)d_in[7];
    const float* b11  = (const float*)d_in[8];
    const float* w12  = (const float*)d_in[9];
    const float* b12  = (const float*)d_in[10];
    const float* wqkv = (const float*)d_in[11];
    const float* bqkv = (const float*)d_in[12];
    const float* wo   = (const float*)d_in[13];
    const float* bo   = (const float*)d_in[14];
    const float* gp   = (const float*)d_in[15];
    const float* ent  = (const float*)d_in[16];
    const float* nw1  = (const float*)d_in[17];
    const float* nb1  = (const float*)d_in[18];
    const float* nw2  = (const float*)d_in[19];
    const float* nb2  = (const float*)d_in[20];

    float *H, *BUFB, *TENT, *GATEB;
    cudaGetSymbolAddress((void**)&H,     g_h);
    cudaGetSymbolAddress((void**)&BUFB,  g_bufs);
    cudaGetSymbolAddress((void**)&TENT,  g_tent);
    cudaGetSymbolAddress((void**)&GATEB, g_gate);
    float* BUF[3];
    for (int k = 0; k < 3; k++) BUF[k] = BUFB + (size_t)k * BATCH_N * QDIM;
    float* LIN = GATEB + 0 * 8 * QDIM;
    float* P3  = GATEB + 1 * 8 * QDIM;
    float* P4  = GATEB + 2 * 8 * QDIM;
    float* P5  = GATEB + 3 * 8 * QDIM;

    prep_k<<<(8 * QDIM * QDIM + 255) / 256, 256>>>(ent, gp, TENT, LIN, P3, P4, P5);

    float* cur = (float*)x;
    for (int li = 0; li < 8; li++) {
        // pick the two rotating buffers not currently holding `cur` (the residual)
        float* s[2]; int cnt = 0;
        for (int k = 0; k < 3; k++)
            if (BUF[k] != cur && cnt < 2) s[cnt++] = BUF[k];

        const int t = li % 3;
        float *mid, *c2;
        EpiParams e0 = {};
        if (t == 0) {
            const int i = li / 3;
            e0.bias = b01 + i * 768;
            launch_gemm(E_BIAS, cur, QDIM, w01 + (size_t)i * QDIM * 768, 768, H, 768, QDIM, 768, e0);
            ln_gelu_k<<<BATCH_N, 256>>>(H, lnw + i * 768, lnb + i * 768);
            e0.bias = b02 + i * QDIM;
            launch_gemm(E_BIAS, H, 768, w02 + (size_t)i * 768 * QDIM, QDIM, s[0], QDIM, 768, QDIM, e0);
            mid = s[0]; c2 = s[1];
        } else if (t == 1) {
            const int i = (li - 1) / 3;
            e0.bias = b11 + i * 512;
            launch_gemm(E_SILU, cur, QDIM, w11 + (size_t)i * QDIM * 512, 512, H, 512, QDIM, 512, e0);
            e0.bias = b12 + i * QDIM;
            launch_gemm(E_BIAS, H, 512, w12 + (size_t)i * 512 * QDIM, QDIM, s[0], QDIM, 512, QDIM, e0);
            mid = s[0]; c2 = s[1];
        } else {
            const int i = (li - 2) / 3;
            // only the V slice of qkv matters: columns [512, 768)
            e0.bias = bqkv + i * 768 + 512;
            launch_gemm(E_BIAS, cur, QDIM, wqkv + (size_t)i * QDIM * 768 + 512, 768, s[0], QDIM, QDIM, QDIM, e0);
            e0.bias = bo + i * QDIM;
            launch_gemm(E_BIAS, s[0], QDIM, wo + (size_t)i * QDIM * QDIM, QDIM, s[1], QDIM, QDIM, QDIM, e0);
            mid = s[1]; c2 = s[0];  // v (s[0]) is dead after this; reuse for c2
        }

        const int odd = li & 1;
        const float alpha = (li < 4) ? 0.8f : 0.6f;

        // entangled = mid @ tanh(ent[li]); epilogue fuses gate + combine (+ alpha blend on even layers)
        EpiParams eg = {};
        eg.cmat = mid; eg.resmat = cur;
        eg.lin = LIN + li * QDIM; eg.p3 = P3 + li * QDIM;
        eg.p4 = P4 + li * QDIM;   eg.p5 = P5 + li * QDIM;
        eg.alpha = alpha; eg.blend = !odd;
        launch_gemm(E_GATE, mid, QDIM, TENT + (size_t)li * QDIM * QDIM, QDIM, c2, QDIM, QDIM, QDIM, eg);

        if (odd) {
            const int j = li / 2;
            EpiParams et = {}; et.bias = nb1 + j * QDIM;
            launch_gemm(E_TANH, c2, QDIM, nw1 + (size_t)j * QDIM * QDIM, QDIM, H, QDIM, QDIM, QDIM, et);
            EpiParams en = {}; en.bias = nb2 + j * QDIM;
            en.cmat = c2; en.resmat = cur; en.alpha = alpha;
            launch_gemm(E_NL, H, QDIM, nw2 + (size_t)j * QDIM * QDIM, QDIM, c2, QDIM, QDIM, QDIM, en);
        }

        float* dst = (li == 7) ? (float*)d_out : c2;
        norm_tanh_k<<<BATCH_N / 8, 256>>>(c2, dst);
        cur = dst;
    }
}